// round 9
// baseline (speedup 1.0000x reference)
#include <cuda_runtime.h>
#include <cstdint>

// Problem constants (fixed shapes)
#define N_NODES 10000
#define R_REL   100
#define E_PER   5000
#define NE      (R_REL * E_PER)      // 500000 edges
#define D_IN    2048
#define D0      128
#define D1      64
#define D2      20
#define NB      8
#define XB1_W   (NB * D1 + D1)       // 512 basis cols + 64 root cols = 576
#define XB2_W   (NB * D2 + D2)       // 160 + 20 = 180

// ---------------- scratch (static device globals; no allocation) -------------
__device__ float g_X  [N_NODES * D0];        // x_drug @ drug_w
__device__ float g_XB1[N_NODES * XB1_W];     // X @ [basis1 flat | root1]
__device__ float g_h  [N_NODES * D1];        // layer-1 output (pre-relu; relu fused into GEMM2 A-load)
__device__ float g_XB2[N_NODES * XB2_W];     // relu(h) @ [basis2 flat | root2]
__device__ int   g_deg[R_REL * N_NODES];     // per (relation, dst) in-degree
__device__ float g_B1 [D0 * XB1_W];          // repacked [basis1|root1] as K x N
__device__ float g_B2 [D1 * XB2_W];          // repacked [basis2|root2] as K x N

// ---------------- trivial kernels -------------------------------------------
__global__ void zero_deg_kernel() {
    int i = blockIdx.x * blockDim.x + threadIdx.x;
    if (i < R_REL * N_NODES) g_deg[i] = 0;
}

__global__ void count_deg_kernel(const int* __restrict__ ei) {
    int i = blockIdx.x * blockDim.x + threadIdx.x;
    if (i >= NE) return;
    int r = i / E_PER;
    int e = i - r * E_PER;
    int dst = __ldg(ei + r * (2 * E_PER) + E_PER + e);
    atomicAdd(&g_deg[r * N_NODES + dst], 1);
}

// pack [basis1 (8,128,64) | root1 (128,64)] into row-major (128, 576)
__global__ void pack_b1_kernel(const float* __restrict__ basis1,
                               const float* __restrict__ root1) {
    int idx = blockIdx.x * blockDim.x + threadIdx.x;
    if (idx >= D0 * XB1_W) return;
    int i = idx / XB1_W;
    int j = idx - i * XB1_W;
    float v;
    if (j < NB * D1) {
        int b = j / D1, o = j - b * D1;
        v = basis1[(b * D0 + i) * D1 + o];
    } else {
        v = root1[i * D1 + (j - NB * D1)];
    }
    g_B1[idx] = v;
}

// pack [basis2 (8,64,20) | root2 (64,20)] into row-major (64, 180)
__global__ void pack_b2_kernel(const float* __restrict__ basis2,
                               const float* __restrict__ root2) {
    int idx = blockIdx.x * blockDim.x + threadIdx.x;
    if (idx >= D1 * XB2_W) return;
    int i = idx / XB2_W;
    int j = idx - i * XB2_W;
    float v;
    if (j < NB * D2) {
        int b = j / D2, o = j - b * D2;
        v = basis2[(b * D1 + i) * D2 + o];
    } else {
        v = root2[i * D2 + (j - NB * D2)];
    }
    g_B2[idx] = v;
}

__global__ void init_h_kernel(const float* __restrict__ bias1) {
    int i = blockIdx.x * blockDim.x + threadIdx.x;
    if (i >= N_NODES * D1) return;
    int n = i / D1, o = i - n * D1;
    g_h[i] = g_XB1[n * XB1_W + NB * D1 + o] + bias1[o];
}

__global__ void init_out_kernel(float* __restrict__ out, const float* __restrict__ bias2) {
    int i = blockIdx.x * blockDim.x + threadIdx.x;
    if (i >= N_NODES * D2) return;
    int n = i / D2, o = i - n * D2;
    out[i] = g_XB2[n * XB2_W + NB * D2 + o] + bias2[o];
}

// ---------------- tiled fp32 GEMM: C(M,N) = op(A)(M,K) @ B(K,N) --------------
// 64x64 tile, 16-wide K steps, 256 threads, 4x4 microtile, float4 everywhere.
// Register-prefetch pipeline: next k-tile's global loads issue before the FMA
// block of the current k-tile, hiding global latency behind 256 FMA/thread.
// RELU_A applies relu to A elements at load (used for layer-2 input).
// Requires K % 16 == 0, N % 4 == 0 (holds for all 3 calls).
template<bool RELU_A>
__global__ void __launch_bounds__(256)
gemm64_kernel(const float* __restrict__ A, const float* __restrict__ B,
              float* __restrict__ C, int M, int N, int K) {
    __shared__ float As[16][68];   // transposed A tile, padded stride (16B aligned)
    __shared__ float Bs[16][64];

    const int t  = threadIdx.x;
    const int tx = t & 15, ty = t >> 4;
    const int row0 = blockIdx.x * 64, col0 = blockIdx.y * 64;

    const int aRow = t >> 2;            // 0..63
    const int aCol = (t & 3) << 2;      // 0,4,8,12
    const int bRow = t >> 4;            // 0..15
    const int bCol = (t & 15) << 2;     // 0..60
    const int gr = row0 + aRow;
    const int gcB = col0 + bCol;

    float acc[4][4];
#pragma unroll
    for (int i = 0; i < 4; i++)
#pragma unroll
        for (int j = 0; j < 4; j++) acc[i][j] = 0.0f;

    // preload first k-tile into registers
    float4 av = make_float4(0.f, 0.f, 0.f, 0.f);
    float4 bv = make_float4(0.f, 0.f, 0.f, 0.f);
    if (gr < M)
        av = *reinterpret_cast<const float4*>(A + (size_t)gr * K + aCol);
    if (gcB < N)
        bv = *reinterpret_cast<const float4*>(B + (size_t)bRow * N + gcB);

    for (int k0 = 0; k0 < K; k0 += 16) {
        if (RELU_A) {
            av.x = fmaxf(av.x, 0.f); av.y = fmaxf(av.y, 0.f);
            av.z = fmaxf(av.z, 0.f); av.w = fmaxf(av.w, 0.f);
        }
        As[aCol + 0][aRow] = av.x;
        As[aCol + 1][aRow] = av.y;
        As[aCol + 2][aRow] = av.z;
        As[aCol + 3][aRow] = av.w;
        *reinterpret_cast<float4*>(&Bs[bRow][bCol]) = bv;

        __syncthreads();

        // prefetch next k-tile while computing this one (global reads only;
        // no hazard with the smem written above)
        if (k0 + 16 < K) {
            if (gr < M)
                av = *reinterpret_cast<const float4*>(A + (size_t)gr * K + (k0 + 16) + aCol);
            if (gcB < N)
                bv = *reinterpret_cast<const float4*>(B + (size_t)(k0 + 16 + bRow) * N + gcB);
        }

#pragma unroll
        for (int kk = 0; kk < 16; kk++) {
            float4 a = *reinterpret_cast<const float4*>(&As[kk][ty << 2]);
            float4 b = *reinterpret_cast<const float4*>(&Bs[kk][tx << 2]);
            acc[0][0] += a.x * b.x; acc[0][1] += a.x * b.y; acc[0][2] += a.x * b.z; acc[0][3] += a.x * b.w;
            acc[1][0] += a.y * b.x; acc[1][1] += a.y * b.y; acc[1][2] += a.y * b.z; acc[1][3] += a.y * b.w;
            acc[2][0] += a.z * b.x; acc[2][1] += a.z * b.y; acc[2][2] += a.z * b.z; acc[2][3] += a.z * b.w;
            acc[3][0] += a.w * b.x; acc[3][1] += a.w * b.y; acc[3][2] += a.w * b.z; acc[3][3] += a.w * b.w;
        }
        __syncthreads();
    }

    int gc = col0 + (tx << 2);
    if (gc < N) {
#pragma unroll
        for (int i = 0; i < 4; i++) {
            int r = row0 + (ty << 2) + i;
            if (r < M)
                *reinterpret_cast<float4*>(C + (size_t)r * N + gc) =
                    make_float4(acc[i][0], acc[i][1], acc[i][2], acc[i][3]);
        }
    }
}

// ---------------- edge message kernels ---------------------------------------
// Layer 1: 16 threads per edge, each thread owns 4 of 64 outputs.
// msg[o] = (1/deg[r,dst]) * sum_b comp1[r,b] * XB1[src, b*64 + o]
__global__ void __launch_bounds__(256)
edge1_kernel(const int* __restrict__ ei, const float* __restrict__ comp1) {
    int lane = threadIdx.x & 15;
    int eid  = blockIdx.x * 16 + (threadIdx.x >> 4);
    if (eid >= NE) return;
    int r = eid / E_PER;
    int e = eid - r * E_PER;
    int src = __ldg(ei + r * (2 * E_PER) + e);
    int dst = __ldg(ei + r * (2 * E_PER) + E_PER + e);
    float inv = __fdividef(1.0f, (float)g_deg[r * N_NODES + dst]);

    const float* xb = g_XB1 + (size_t)src * XB1_W;
    float4 acc = make_float4(0.f, 0.f, 0.f, 0.f);
#pragma unroll
    for (int b = 0; b < NB; b++) {
        float w = __ldg(comp1 + r * NB + b);
        float4 v = *reinterpret_cast<const float4*>(xb + b * D1 + (lane << 2));
        acc.x += w * v.x; acc.y += w * v.y; acc.z += w * v.z; acc.w += w * v.w;
    }
    acc.x *= inv; acc.y *= inv; acc.z *= inv; acc.w *= inv;
    float* p = g_h + (size_t)dst * D1 + (lane << 2);
    asm volatile("red.global.add.v4.f32 [%0], {%1,%2,%3,%4};"
                 :: "l"(p), "f"(acc.x), "f"(acc.y), "f"(acc.z), "f"(acc.w) : "memory");
}

// Layer 2: 8 threads per edge, lanes 0..4 each own 4 of 20 outputs.
__global__ void __launch_bounds__(256)
edge2_kernel(const int* __restrict__ ei, const float* __restrict__ comp2,
             float* __restrict__ out) {
    int lane = threadIdx.x & 7;
    int eid  = blockIdx.x * 32 + (threadIdx.x >> 3);
    if (eid >= NE || lane >= 5) return;
    int r = eid / E_PER;
    int e = eid - r * E_PER;
    int src = __ldg(ei + r * (2 * E_PER) + e);
    int dst = __ldg(ei + r * (2 * E_PER) + E_PER + e);
    float inv = __fdividef(1.0f, (float)g_deg[r * N_NODES + dst]);

    const float* xb = g_XB2 + (size_t)src * XB2_W;
    float4 acc = make_float4(0.f, 0.f, 0.f, 0.f);
#pragma unroll
    for (int b = 0; b < NB; b++) {
        float w = __ldg(comp2 + r * NB + b);
        float4 v = *reinterpret_cast<const float4*>(xb + b * D2 + (lane << 2));
        acc.x += w * v.x; acc.y += w * v.y; acc.z += w * v.z; acc.w += w * v.w;
    }
    acc.x *= inv; acc.y *= inv; acc.z *= inv; acc.w *= inv;
    float* p = out + (size_t)dst * D2 + (lane << 2);
    asm volatile("red.global.add.v4.f32 [%0], {%1,%2,%3,%4};"
                 :: "l"(p), "f"(acc.x), "f"(acc.y), "f"(acc.z), "f"(acc.w) : "memory");
}

// ---------------- launch ------------------------------------------------------
extern "C" void kernel_launch(void* const* d_in, const int* in_sizes, int n_in,
                              void* d_out, int out_size) {
    const float* x_drug = (const float*)d_in[0];
    const float* drug_w = (const float*)d_in[1];
    const int*   ei     = (const int*)  d_in[2];
    const float* basis1 = (const float*)d_in[3];
    const float* comp1  = (const float*)d_in[4];
    const float* root1  = (const float*)d_in[5];
    const float* bias1  = (const float*)d_in[6];
    const float* basis2 = (const float*)d_in[7];
    const float* comp2  = (const float*)d_in[8];
    const float* root2  = (const float*)d_in[9];
    const float* bias2  = (const float*)d_in[10];
    float* out = (float*)d_out;

    float* X;   cudaGetSymbolAddress((void**)&X,   g_X);
    float* XB1; cudaGetSymbolAddress((void**)&XB1, g_XB1);
    float* H;   cudaGetSymbolAddress((void**)&H,   g_h);
    float* XB2; cudaGetSymbolAddress((void**)&XB2, g_XB2);
    float* B1;  cudaGetSymbolAddress((void**)&B1,  g_B1);
    float* B2;  cudaGetSymbolAddress((void**)&B2,  g_B2);

    const int T = 256;

    // degree (shared by both layers)
    zero_deg_kernel<<<(R_REL * N_NODES + T - 1) / T, T>>>();
    count_deg_kernel<<<(NE + T - 1) / T, T>>>(ei);

    // weight repacks
    pack_b1_kernel<<<(D0 * XB1_W + T - 1) / T, T>>>(basis1, root1);
    pack_b2_kernel<<<(D1 * XB2_W + T - 1) / T, T>>>(basis2, root2);

    // X = x_drug @ drug_w            (10000 x 2048) @ (2048 x 128)
    gemm64_kernel<false><<<dim3((N_NODES + 63) / 64, (D0 + 63) / 64), T>>>(
        x_drug, drug_w, X, N_NODES, D0, D_IN);

    // XB1 = X @ [basis1|root1]       (10000 x 128) @ (128 x 576)
    gemm64_kernel<false><<<dim3((N_NODES + 63) / 64, (XB1_W + 63) / 64), T>>>(
        X, B1, XB1, N_NODES, XB1_W, D0);

    // h = root part + bias1, then edge messages (relu deferred into GEMM2 A-load)
    init_h_kernel<<<(N_NODES * D1 + T - 1) / T, T>>>(bias1);
    edge1_kernel<<<(NE + 15) / 16, T>>>(ei, comp1);

    // XB2 = relu(h) @ [basis2|root2] (10000 x 64) @ (64 x 180), relu fused into A-load
    gemm64_kernel<true><<<dim3((N_NODES + 63) / 64, (XB2_W + 63) / 64), T>>>(
        H, B2, XB2, N_NODES, XB2_W, D1);

    // out = root part + bias2, then edge messages
    init_out_kernel<<<(N_NODES * D2 + T - 1) / T, T>>>(out, bias2);
    edge2_kernel<<<(NE + 31) / 32, T>>>(ei, comp2, out);
}

// round 11
// speedup vs baseline: 1.1401x; 1.1401x over previous
#include <cuda_runtime.h>
#include <cstdint>

// Problem constants (fixed shapes)
#define N_NODES 10000
#define R_REL   100
#define E_PER   5000
#define NE      (R_REL * E_PER)      // 500000 edges
#define D_IN    2048
#define D0      128
#define D1      64
#define D2      20
#define NB      8
#define XB1_W   (NB * D1 + D1)       // 512 basis cols + 64 root cols = 576
#define XB2_W   (NB * D2 + D2)       // 160 + 20 = 180

// ---------------- scratch (static device globals; no allocation) -------------
__device__ float g_X  [N_NODES * D0];        // x_drug @ drug_w
__device__ float g_XB1[N_NODES * XB1_W];     // X @ [basis1 flat | root1]
__device__ float g_h  [N_NODES * D1];        // layer-1 output (pre-relu; relu fused into GEMM3 A-load)
__device__ float g_XB2[N_NODES * XB2_W];     // relu(h) @ [basis2 flat | root2]
__device__ int   g_deg[R_REL * N_NODES];     // per (relation, dst) in-degree
__device__ float g_B1 [D0 * XB1_W];          // repacked [basis1|root1] as K x N
__device__ float g_B2 [D1 * XB2_W];          // repacked [basis2|root2] as K x N

// ---------------- trivial kernels -------------------------------------------
__global__ void zero_deg_kernel() {
    int i = blockIdx.x * blockDim.x + threadIdx.x;
    if (i < R_REL * N_NODES) g_deg[i] = 0;
}

__global__ void count_deg_kernel(const int* __restrict__ ei) {
    int i = blockIdx.x * blockDim.x + threadIdx.x;
    if (i >= NE) return;
    int r = i / E_PER;
    int e = i - r * E_PER;
    int dst = __ldg(ei + r * (2 * E_PER) + E_PER + e);
    atomicAdd(&g_deg[r * N_NODES + dst], 1);
}

// pack [basis1 (8,128,64) | root1 (128,64)] into row-major (128, 576)
__global__ void pack_b1_kernel(const float* __restrict__ basis1,
                               const float* __restrict__ root1) {
    int idx = blockIdx.x * blockDim.x + threadIdx.x;
    if (idx >= D0 * XB1_W) return;
    int i = idx / XB1_W;
    int j = idx - i * XB1_W;
    float v;
    if (j < NB * D1) {
        int b = j / D1, o = j - b * D1;
        v = basis1[(b * D0 + i) * D1 + o];
    } else {
        v = root1[i * D1 + (j - NB * D1)];
    }
    g_B1[idx] = v;
}

// pack [basis2 (8,64,20) | root2 (64,20)] into row-major (64, 180)
__global__ void pack_b2_kernel(const float* __restrict__ basis2,
                               const float* __restrict__ root2) {
    int idx = blockIdx.x * blockDim.x + threadIdx.x;
    if (idx >= D1 * XB2_W) return;
    int i = idx / XB2_W;
    int j = idx - i * XB2_W;
    float v;
    if (j < NB * D2) {
        int b = j / D2, o = j - b * D2;
        v = basis2[(b * D1 + i) * D2 + o];
    } else {
        v = root2[i * D2 + (j - NB * D2)];
    }
    g_B2[idx] = v;
}

__global__ void init_h_kernel(const float* __restrict__ bias1) {
    int i = blockIdx.x * blockDim.x + threadIdx.x;
    if (i >= N_NODES * D1) return;
    int n = i / D1, o = i - n * D1;
    g_h[i] = g_XB1[n * XB1_W + NB * D1 + o] + bias1[o];
}

__global__ void init_out_kernel(float* __restrict__ out, const float* __restrict__ bias2) {
    int i = blockIdx.x * blockDim.x + threadIdx.x;
    if (i >= N_NODES * D2) return;
    int n = i / D2, o = i - n * D2;
    out[i] = g_XB2[n * XB2_W + NB * D2 + o] + bias2[o];
}

// ---------------- tf32 helpers ------------------------------------------------
__device__ __forceinline__ unsigned f2tf32(float f) {
    unsigned u;
    asm("cvt.rna.tf32.f32 %0, %1;" : "=r"(u) : "f"(f));
    return u;
}
__device__ __forceinline__ void split_tf32(float f, unsigned& hi, unsigned& lo) {
    hi = f2tf32(f);
    float r = f - __uint_as_float(hi);
    lo = f2tf32(r);
}
__device__ __forceinline__ void mma_tf32(float* c, const unsigned* a, const unsigned* b) {
    asm volatile(
        "mma.sync.aligned.m16n8k8.row.col.f32.tf32.tf32.f32 "
        "{%0,%1,%2,%3}, {%4,%5,%6,%7}, {%8,%9}, {%0,%1,%2,%3};"
        : "+f"(c[0]), "+f"(c[1]), "+f"(c[2]), "+f"(c[3])
        : "r"(a[0]), "r"(a[1]), "r"(a[2]), "r"(a[3]), "r"(b[0]), "r"(b[1]));
}

// ---------------- 3xTF32 tensor GEMM: C(M,N) = A(M,K) @ B(K,N) ---------------
// 64x64 CTA tile, BK=16, 256 threads = 8 warps (2x4), warp tile 32x16.
// Each float operand is split hi/lo in tf32; 3 mma per logical mma keeps
// near-fp32 accuracy. Register-prefetch of the next k-tile over compute.
// Requires K % 16 == 0, N % 4 == 0, N tile-exact in 64 at call sites.
#define TBM 64
#define TBN 64
#define TBK 16
#define AS_STR 20   // As[m][k], stride 20 -> conflict-free fragment loads
#define BS_STR 72   // Bs[k][n], stride 72 -> (8k+n)%32 all-distinct

__global__ void __launch_bounds__(256)
gemm_tf32_kernel(const float* __restrict__ A, const float* __restrict__ B,
                 float* __restrict__ C, int M, int N, int K) {
    __shared__ float As[TBM][AS_STR];
    __shared__ float Bs[TBK][BS_STR];

    const int t = threadIdx.x;
    const int lane = t & 31;
    const int wid  = t >> 5;
    const int warp_m = wid & 1;        // m offset 32*warp_m
    const int warp_n = wid >> 1;       // n offset 16*warp_n

    const int m_cta = blockIdx.x * TBM;
    const int n_cta = blockIdx.y * TBN;

    const int aRow = t >> 2;           // 0..63
    const int aCol = (t & 3) << 2;     // 0,4,8,12
    const int bRow = t >> 4;           // 0..15
    const int bCol = (t & 15) << 2;    // 0..60
    const int gr = m_cta + aRow;
    const int gc = n_cta + bCol;

    float acc[2][2][4];
#pragma unroll
    for (int mi = 0; mi < 2; mi++)
#pragma unroll
        for (int ni = 0; ni < 2; ni++)
#pragma unroll
            for (int k = 0; k < 4; k++) acc[mi][ni][k] = 0.0f;

    // preload first k-tile
    float4 av = make_float4(0.f, 0.f, 0.f, 0.f);
    float4 bv = make_float4(0.f, 0.f, 0.f, 0.f);
    if (gr < M) av = *reinterpret_cast<const float4*>(A + (size_t)gr * K + aCol);
    if (gc < N) bv = *reinterpret_cast<const float4*>(B + (size_t)bRow * N + gc);

    const int KITERS = K / TBK;
    for (int kt = 0; kt < KITERS; kt++) {
        *reinterpret_cast<float4*>(&As[aRow][aCol]) = av;
        *reinterpret_cast<float4*>(&Bs[bRow][bCol]) = bv;
        __syncthreads();

        // prefetch next k-tile (global only; no smem hazard)
        if (kt + 1 < KITERS) {
            int kn = (kt + 1) * TBK;
            if (gr < M) av = *reinterpret_cast<const float4*>(A + (size_t)gr * K + kn + aCol);
            if (gc < N) bv = *reinterpret_cast<const float4*>(B + (size_t)(kn + bRow) * N + gc);
        }

#pragma unroll
        for (int ks = 0; ks < 2; ks++) {
            const int k0 = ks * 8;
            // B fragments (8x8 col-major): b0 row=lane%4, b1 row=lane%4+4, col=lane/4
            unsigned bhi[2][2], blo[2][2];
#pragma unroll
            for (int ni = 0; ni < 2; ni++) {
                int n0 = warp_n * 16 + ni * 8 + (lane >> 2);
                float b0 = Bs[k0 + (lane & 3)][n0];
                float b1 = Bs[k0 + (lane & 3) + 4][n0];
                split_tf32(b0, bhi[ni][0], blo[ni][0]);
                split_tf32(b1, bhi[ni][1], blo[ni][1]);
            }
#pragma unroll
            for (int mi = 0; mi < 2; mi++) {
                // A fragments (16x8 row-major)
                int m0 = warp_m * 32 + mi * 16 + (lane >> 2);
                float a0 = As[m0    ][k0 + (lane & 3)    ];
                float a1 = As[m0 + 8][k0 + (lane & 3)    ];
                float a2 = As[m0    ][k0 + (lane & 3) + 4];
                float a3 = As[m0 + 8][k0 + (lane & 3) + 4];
                unsigned ahi[4], alo[4];
                split_tf32(a0, ahi[0], alo[0]);
                split_tf32(a1, ahi[1], alo[1]);
                split_tf32(a2, ahi[2], alo[2]);
                split_tf32(a3, ahi[3], alo[3]);
#pragma unroll
                for (int ni = 0; ni < 2; ni++) {
                    mma_tf32(acc[mi][ni], ahi, bhi[ni]);
                    mma_tf32(acc[mi][ni], alo, bhi[ni]);
                    mma_tf32(acc[mi][ni], ahi, blo[ni]);
                }
            }
        }
        __syncthreads();
    }

    // epilogue: c0/c1 at (row, 2c), (row, 2c+1); c2/c3 at row+8
#pragma unroll
    for (int mi = 0; mi < 2; mi++) {
        int row = m_cta + warp_m * 32 + mi * 16 + (lane >> 2);
#pragma unroll
        for (int ni = 0; ni < 2; ni++) {
            int col = n_cta + warp_n * 16 + ni * 8 + (lane & 3) * 2;
            if (row < M)
                *reinterpret_cast<float2*>(C + (size_t)row * N + col) =
                    make_float2(acc[mi][ni][0], acc[mi][ni][1]);
            if (row + 8 < M)
                *reinterpret_cast<float2*>(C + (size_t)(row + 8) * N + col) =
                    make_float2(acc[mi][ni][2], acc[mi][ni][3]);
        }
    }
}

// ---------------- tiled fp32 GEMM (kept for small GEMM3 with fused relu) -----
template<bool RELU_A>
__global__ void __launch_bounds__(256)
gemm64_kernel(const float* __restrict__ A, const float* __restrict__ B,
              float* __restrict__ C, int M, int N, int K) {
    __shared__ float As[16][68];
    __shared__ float Bs[16][64];

    const int t  = threadIdx.x;
    const int tx = t & 15, ty = t >> 4;
    const int row0 = blockIdx.x * 64, col0 = blockIdx.y * 64;

    const int aRow = t >> 2;
    const int aCol = (t & 3) << 2;
    const int bRow = t >> 4;
    const int bCol = (t & 15) << 2;
    const int gr = row0 + aRow;
    const int gcB = col0 + bCol;

    float acc[4][4];
#pragma unroll
    for (int i = 0; i < 4; i++)
#pragma unroll
        for (int j = 0; j < 4; j++) acc[i][j] = 0.0f;

    float4 av = make_float4(0.f, 0.f, 0.f, 0.f);
    float4 bv = make_float4(0.f, 0.f, 0.f, 0.f);
    if (gr < M)
        av = *reinterpret_cast<const float4*>(A + (size_t)gr * K + aCol);
    if (gcB < N)
        bv = *reinterpret_cast<const float4*>(B + (size_t)bRow * N + gcB);

    for (int k0 = 0; k0 < K; k0 += 16) {
        if (RELU_A) {
            av.x = fmaxf(av.x, 0.f); av.y = fmaxf(av.y, 0.f);
            av.z = fmaxf(av.z, 0.f); av.w = fmaxf(av.w, 0.f);
        }
        As[aCol + 0][aRow] = av.x;
        As[aCol + 1][aRow] = av.y;
        As[aCol + 2][aRow] = av.z;
        As[aCol + 3][aRow] = av.w;
        *reinterpret_cast<float4*>(&Bs[bRow][bCol]) = bv;

        __syncthreads();

        if (k0 + 16 < K) {
            if (gr < M)
                av = *reinterpret_cast<const float4*>(A + (size_t)gr * K + (k0 + 16) + aCol);
            if (gcB < N)
                bv = *reinterpret_cast<const float4*>(B + (size_t)(k0 + 16 + bRow) * N + gcB);
        }

#pragma unroll
        for (int kk = 0; kk < 16; kk++) {
            float4 a = *reinterpret_cast<const float4*>(&As[kk][ty << 2]);
            float4 b = *reinterpret_cast<const float4*>(&Bs[kk][tx << 2]);
            acc[0][0] += a.x * b.x; acc[0][1] += a.x * b.y; acc[0][2] += a.x * b.z; acc[0][3] += a.x * b.w;
            acc[1][0] += a.y * b.x; acc[1][1] += a.y * b.y; acc[1][2] += a.y * b.z; acc[1][3] += a.y * b.w;
            acc[2][0] += a.z * b.x; acc[2][1] += a.z * b.y; acc[2][2] += a.z * b.z; acc[2][3] += a.z * b.w;
            acc[3][0] += a.w * b.x; acc[3][1] += a.w * b.y; acc[3][2] += a.w * b.z; acc[3][3] += a.w * b.w;
        }
        __syncthreads();
    }

    int gc = col0 + (tx << 2);
    if (gc < N) {
#pragma unroll
        for (int i = 0; i < 4; i++) {
            int r = row0 + (ty << 2) + i;
            if (r < M)
                *reinterpret_cast<float4*>(C + (size_t)r * N + gc) =
                    make_float4(acc[i][0], acc[i][1], acc[i][2], acc[i][3]);
        }
    }
}

// ---------------- edge message kernels ---------------------------------------
__global__ void __launch_bounds__(256)
edge1_kernel(const int* __restrict__ ei, const float* __restrict__ comp1) {
    int lane = threadIdx.x & 15;
    int eid  = blockIdx.x * 16 + (threadIdx.x >> 4);
    if (eid >= NE) return;
    int r = eid / E_PER;
    int e = eid - r * E_PER;
    int src = __ldg(ei + r * (2 * E_PER) + e);
    int dst = __ldg(ei + r * (2 * E_PER) + E_PER + e);
    float inv = __fdividef(1.0f, (float)g_deg[r * N_NODES + dst]);

    const float* xb = g_XB1 + (size_t)src * XB1_W;
    float4 acc = make_float4(0.f, 0.f, 0.f, 0.f);
#pragma unroll
    for (int b = 0; b < NB; b++) {
        float w = __ldg(comp1 + r * NB + b);
        float4 v = *reinterpret_cast<const float4*>(xb + b * D1 + (lane << 2));
        acc.x += w * v.x; acc.y += w * v.y; acc.z += w * v.z; acc.w += w * v.w;
    }
    acc.x *= inv; acc.y *= inv; acc.z *= inv; acc.w *= inv;
    float* p = g_h + (size_t)dst * D1 + (lane << 2);
    asm volatile("red.global.add.v4.f32 [%0], {%1,%2,%3,%4};"
                 :: "l"(p), "f"(acc.x), "f"(acc.y), "f"(acc.z), "f"(acc.w) : "memory");
}

__global__ void __launch_bounds__(256)
edge2_kernel(const int* __restrict__ ei, const float* __restrict__ comp2,
             float* __restrict__ out) {
    int lane = threadIdx.x & 7;
    int eid  = blockIdx.x * 32 + (threadIdx.x >> 3);
    if (eid >= NE || lane >= 5) return;
    int r = eid / E_PER;
    int e = eid - r * E_PER;
    int src = __ldg(ei + r * (2 * E_PER) + e);
    int dst = __ldg(ei + r * (2 * E_PER) + E_PER + e);
    float inv = __fdividef(1.0f, (float)g_deg[r * N_NODES + dst]);

    const float* xb = g_XB2 + (size_t)src * XB2_W;
    float4 acc = make_float4(0.f, 0.f, 0.f, 0.f);
#pragma unroll
    for (int b = 0; b < NB; b++) {
        float w = __ldg(comp2 + r * NB + b);
        float4 v = *reinterpret_cast<const float4*>(xb + b * D2 + (lane << 2));
        acc.x += w * v.x; acc.y += w * v.y; acc.z += w * v.z; acc.w += w * v.w;
    }
    acc.x *= inv; acc.y *= inv; acc.z *= inv; acc.w *= inv;
    float* p = out + (size_t)dst * D2 + (lane << 2);
    asm volatile("red.global.add.v4.f32 [%0], {%1,%2,%3,%4};"
                 :: "l"(p), "f"(acc.x), "f"(acc.y), "f"(acc.z), "f"(acc.w) : "memory");
}

// ---------------- launch ------------------------------------------------------
extern "C" void kernel_launch(void* const* d_in, const int* in_sizes, int n_in,
                              void* d_out, int out_size) {
    const float* x_drug = (const float*)d_in[0];
    const float* drug_w = (const float*)d_in[1];
    const int*   ei     = (const int*)  d_in[2];
    const float* basis1 = (const float*)d_in[3];
    const float* comp1  = (const float*)d_in[4];
    const float* root1  = (const float*)d_in[5];
    const float* bias1  = (const float*)d_in[6];
    const float* basis2 = (const float*)d_in[7];
    const float* comp2  = (const float*)d_in[8];
    const float* root2  = (const float*)d_in[9];
    const float* bias2  = (const float*)d_in[10];
    float* out = (float*)d_out;

    float* X;   cudaGetSymbolAddress((void**)&X,   g_X);
    float* XB1; cudaGetSymbolAddress((void**)&XB1, g_XB1);
    float* H;   cudaGetSymbolAddress((void**)&H,   g_h);
    float* XB2; cudaGetSymbolAddress((void**)&XB2, g_XB2);
    float* B1;  cudaGetSymbolAddress((void**)&B1,  g_B1);
    float* B2;  cudaGetSymbolAddress((void**)&B2,  g_B2);

    const int T = 256;

    // degree (shared by both layers)
    zero_deg_kernel<<<(R_REL * N_NODES + T - 1) / T, T>>>();
    count_deg_kernel<<<(NE + T - 1) / T, T>>>(ei);

    // weight repacks
    pack_b1_kernel<<<(D0 * XB1_W + T - 1) / T, T>>>(basis1, root1);
    pack_b2_kernel<<<(D1 * XB2_W + T - 1) / T, T>>>(basis2, root2);

    // X = x_drug @ drug_w            (10000 x 2048) @ (2048 x 128)   [3xTF32 tensor]
    gemm_tf32_kernel<<<dim3((N_NODES + TBM - 1) / TBM, D0 / TBN), T>>>(
        x_drug, drug_w, X, N_NODES, D0, D_IN);

    // XB1 = X @ [basis1|root1]       (10000 x 128) @ (128 x 576)     [3xTF32 tensor]
    gemm_tf32_kernel<<<dim3((N_NODES + TBM - 1) / TBM, XB1_W / TBN), T>>>(
        X, B1, XB1, N_NODES, XB1_W, D0);

    // h = root part + bias1, then edge messages (relu deferred into GEMM3 A-load)
    init_h_kernel<<<(N_NODES * D1 + T - 1) / T, T>>>(bias1);
    edge1_kernel<<<(NE + 15) / 16, T>>>(ei, comp1);

    // XB2 = relu(h) @ [basis2|root2] (10000 x 64) @ (64 x 180), relu fused into A-load
    gemm64_kernel<true><<<dim3((N_NODES + 63) / 64, (XB2_W + 63) / 64), T>>>(
        H, B2, XB2, N_NODES, XB2_W, D1);

    // out = root part + bias2, then edge messages
    init_out_kernel<<<(N_NODES * D2 + T - 1) / T, T>>>(out, bias2);
    edge2_kernel<<<(NE + 31) / 32, T>>>(ei, comp2, out);
}